// round 3
// baseline (speedup 1.0000x reference)
#include <cuda_runtime.h>

#define BB 2
#define CC 32
#define DD 64
#define HH 128
#define WW 128
#define NBC (BB*CC)
#define NSLICE (BB*CC*DD)

// Per-slice partials: [ssum, sx, sy, sz]. Fully written every run -> no init needed.
__device__ float4 g_part[NSLICE];

// ---- packed f32x2 helpers ----
__device__ __forceinline__ void unpack2(unsigned long long v, float& lo, float& hi) {
    asm("mov.b64 {%0,%1}, %2;" : "=f"(lo), "=f"(hi) : "l"(v));
}

__device__ __forceinline__ void acc2(unsigned long long& acc, unsigned long long v) {
    asm("add.rn.f32x2 %0, %0, %1;" : "+l"(acc) : "l"(v));
}

// acc += |b - a| elementwise on packed f32x2
__device__ __forceinline__ void absdiff_acc2(unsigned long long& acc,
                                             unsigned long long a,
                                             unsigned long long b,
                                             unsigned long long neg1) {
    unsigned long long d;
    asm("fma.rn.f32x2 %0, %1, %2, %3;" : "=l"(d) : "l"(a), "l"(neg1), "l"(b)); // d = b - a
    asm("and.b64 %0, %0, 0x7FFFFFFF7FFFFFFF;" : "+l"(d));                      // |d|
    asm("add.rn.f32x2 %0, %0, %1;" : "+l"(acc) : "l"(d));
}

__device__ __forceinline__ ulonglong2 ldrow(const float* base, int h, int lane) {
    return reinterpret_cast<const ulonglong2*>(base + h * WW)[lane];
}

// One CTA per z-slice. 8 warps; warp w walks rows [16w, 16w+16) sequentially,
// carrying the row in registers so the y-diff needs no second load.
__global__ __launch_bounds__(256) void slice_kernel(const float* __restrict__ seg) {
    const int s = blockIdx.x;
    const int d = s & (DD - 1);

    const float* slice  = seg + (size_t)s * (HH * WW);
    const float* nslice = slice + (HH * WW);          // read only if d < DD-1

    const int warp = threadIdx.x >> 5;
    const int lane = threadIdx.x & 31;
    const bool has_z = (d < DD - 1);

    const unsigned long long neg1 = 0xBF800000BF800000ULL;  // (-1.f, -1.f)

    unsigned long long acc_s = 0ULL, acc_y = 0ULL, acc_z = 0ULL;
    float sx = 0.f;

    const int h0 = warp * 16;
    ulonglong2 row = ldrow(slice, h0, lane);

    #pragma unroll 4
    for (int i = 0; i < 16; i++) {
        const int h = h0 + i;
        const bool hasn = (h < HH - 1);

        ulonglong2 nxt;
        if (hasn) nxt = ldrow(slice, h + 1, lane);

        // slice sum (packed)
        acc2(acc_s, row.x);
        acc2(acc_s, row.y);

        // x-diffs: scalar within float4 + one cross-lane shuffle
        float x0, x1, x2, x3;
        unpack2(row.x, x0, x1);
        unpack2(row.y, x2, x3);
        const float nlx = __shfl_down_sync(0xffffffffu, x0, 1);
        sx += fabsf(x1 - x0) + fabsf(x2 - x1) + fabsf(x3 - x2);
        if (lane < 31) sx += fabsf(nlx - x3);

        // z-diff vs same position in next slice (L2-resident: adjacent CTA's cur)
        if (has_z) {
            const ulonglong2 zn = ldrow(nslice, h, lane);
            absdiff_acc2(acc_z, row.x, zn.x, neg1);
            absdiff_acc2(acc_z, row.y, zn.y, neg1);
        }

        // y-diff vs carried next row
        if (hasn) {
            absdiff_acc2(acc_y, row.x, nxt.x, neg1);
            absdiff_acc2(acc_y, row.y, nxt.y, neg1);
            row = nxt;
        }
    }

    float a, b;
    unpack2(acc_s, a, b); float ssum = a + b;
    unpack2(acc_y, a, b); float sy   = a + b;
    unpack2(acc_z, a, b); float sz   = a + b;

    // warp reduce
    #pragma unroll
    for (int off = 16; off > 0; off >>= 1) {
        ssum += __shfl_xor_sync(0xffffffffu, ssum, off);
        sx   += __shfl_xor_sync(0xffffffffu, sx,   off);
        sy   += __shfl_xor_sync(0xffffffffu, sy,   off);
        sz   += __shfl_xor_sync(0xffffffffu, sz,   off);
    }

    __shared__ float sh[4][8];
    if (lane == 0) { sh[0][warp] = ssum; sh[1][warp] = sx; sh[2][warp] = sy; sh[3][warp] = sz; }
    __syncthreads();

    if (threadIdx.x == 0) {
        float t0 = 0.f, t1 = 0.f, t2 = 0.f, t3 = 0.f;
        #pragma unroll
        for (int w = 0; w < 8; w++) {
            t0 += sh[0][w]; t1 += sh[1][w]; t2 += sh[2][w]; t3 += sh[3][w];
        }
        g_part[s] = make_float4(t0, t1, t2, t3);
    }
}

// 1024 threads, 32 warps. Warp w owns (b,c) rows 2w and 2w+1.
// For a given bc, lane l loads slice d=l (crown half) and d=32+l (root half):
// two independent coalesced float4 loads -> full latency overlap.
__global__ __launch_bounds__(1024) void finalize_kernel(float* __restrict__ out) {
    const int tid  = threadIdx.x;
    const int warp = tid >> 5;
    const int lane = tid & 31;

    __shared__ double s_loss[32], s_tx[32], s_ty[32], s_tz[32];

    double loss_acc = 0.0, tx_acc = 0.0, ty_acc = 0.0, tz_acc = 0.0;

    #pragma unroll
    for (int k = 0; k < 2; k++) {
        const int bc = warp * 2 + k;
        const float4 vc = g_part[bc * DD + lane];        // crown half: d = lane
        const float4 vr = g_part[bc * DD + 32 + lane];   // root half:  d = 32 + lane

        double crown = (double)vc.x;
        double root  = (double)vr.x;
        double tx = (double)vc.y + (double)vr.y;
        double ty = (double)vc.z + (double)vr.z;
        double tz = (double)vc.w + (double)vr.w;

        #pragma unroll
        for (int off = 16; off > 0; off >>= 1) {
            crown += __shfl_xor_sync(0xffffffffu, crown, off);
            root  += __shfl_xor_sync(0xffffffffu, root,  off);
            tx    += __shfl_xor_sync(0xffffffffu, tx,    off);
            ty    += __shfl_xor_sync(0xffffffffu, ty,    off);
            tz    += __shfl_xor_sync(0xffffffffu, tz,    off);
        }

        if ((crown + root) > 0.0 && root > 0.0) {
            const double r = crown / root - 1.2;
            loss_acc += r * r;
        }
        tx_acc += tx; ty_acc += ty; tz_acc += tz;
    }

    if (lane == 0) {
        s_loss[warp] = loss_acc;
        s_tx[warp] = tx_acc; s_ty[warp] = ty_acc; s_tz[warp] = tz_acc;
    }
    __syncthreads();

    if (warp == 0) {
        double L  = s_loss[lane];
        double Tx = s_tx[lane];
        double Ty = s_ty[lane];
        double Tz = s_tz[lane];
        #pragma unroll
        for (int off = 16; off > 0; off >>= 1) {
            L  += __shfl_xor_sync(0xffffffffu, L,  off);
            Tx += __shfl_xor_sync(0xffffffffu, Tx, off);
            Ty += __shfl_xor_sync(0xffffffffu, Ty, off);
            Tz += __shfl_xor_sync(0xffffffffu, Tz, off);
        }
        if (lane == 0) {
            const double cr_loss = L / (double)NBC;
            const double Nx = (double)BB * CC * DD * HH * (WW - 1);
            const double Ny = (double)BB * CC * DD * (HH - 1) * WW;
            const double Nz = (double)BB * CC * (DD - 1) * HH * WW;
            const double tv = Tx / Nx + Ty / Ny + Tz / Nz;

            const double crown_root = cr_loss * 2.0;   // CROWN_ROOT_W
            const double smooth     = tv * 1.5;        // SMOOTH_W
            out[0] = (float)crown_root;
            out[1] = (float)smooth;
            out[2] = (float)(crown_root + smooth);
        }
    }
}

extern "C" void kernel_launch(void* const* d_in, const int* in_sizes, int n_in,
                              void* d_out, int out_size) {
    const float* seg = (const float*)d_in[0];
    float* out = (float*)d_out;

    slice_kernel<<<NSLICE, 256>>>(seg);
    finalize_kernel<<<1, 1024>>>(out);
}

// round 4
// speedup vs baseline: 1.3779x; 1.3779x over previous
#include <cuda_runtime.h>

#define BB 2
#define CC 32
#define DD 64
#define HH 128
#define WW 128
#define NBC (BB*CC)
#define ROWS_PER_CTA 8
#define HBLOCKS (HH/ROWS_PER_CTA)    // 16
#define NCTA (NBC*HBLOCKS)           // 1024
#define SLICE_STRIDE (HH*WW)

// Per-CTA partials, fully rewritten every run. Counter self-resets -> no init kernel.
__device__ float4 g_a[NCTA];         // crown, root, sx, sy
__device__ float  g_b[NCTA];         // sz
__device__ unsigned int g_count;     // zero at load; last CTA resets to 0

// ---- packed f32x2 helpers ----
__device__ __forceinline__ void unpack2(unsigned long long v, float& lo, float& hi) {
    asm("mov.b64 {%0,%1}, %2;" : "=f"(lo), "=f"(hi) : "l"(v));
}
__device__ __forceinline__ void acc2(unsigned long long& acc, unsigned long long v) {
    asm("add.rn.f32x2 %0, %0, %1;" : "+l"(acc) : "l"(v));
}
// acc += |b - a| elementwise on packed f32x2
__device__ __forceinline__ void absdiff_acc2(unsigned long long& acc,
                                             unsigned long long a,
                                             unsigned long long b,
                                             unsigned long long neg1) {
    unsigned long long d;
    asm("fma.rn.f32x2 %0, %1, %2, %3;" : "=l"(d) : "l"(a), "l"(neg1), "l"(b)); // d = b - a
    asm("and.b64 %0, %0, 0x7FFFFFFF7FFFFFFF;" : "+l"(d));                      // |d|
    asm("add.rn.f32x2 %0, %0, %1;" : "+l"(acc) : "l"(d));
}
__device__ __forceinline__ float hadd2(unsigned long long v) {
    float a, b; unpack2(v, a, b); return a + b;
}

// One CTA = (bc, block of 8 rows). Warp w owns row h = hb*8 + w and walks all
// 64 z-slices sequentially, carrying the previous slice's row in registers
// (z-diff = register op, no second global stream). y-diff loads row h+1 at the
// same d — that is another warp's cur in the same CTA -> L1 hit.
__global__ void __launch_bounds__(256, 7) fused_kernel(const float* __restrict__ seg,
                                                       float* __restrict__ out) {
    const int cta  = blockIdx.x;
    const int bc   = cta >> 4;
    const int hb   = cta & (HBLOCKS - 1);
    const int warp = threadIdx.x >> 5;
    const int lane = threadIdx.x & 31;
    const int h    = hb * ROWS_PER_CTA + warp;
    const bool has_y = (h < HH - 1);
    const unsigned long long neg1 = 0xBF800000BF800000ULL;

    const float* p = seg + (size_t)bc * DD * SLICE_STRIDE + h * WW;

    unsigned long long acc_c = 0ULL, acc_r = 0ULL, acc_y = 0ULL, acc_z = 0ULL;
    float sx = 0.f;
    ulonglong2 prev;

    #pragma unroll 2
    for (int d = 0; d < DD; d++) {
        const ulonglong2 cur = reinterpret_cast<const ulonglong2*>(p)[lane];
        ulonglong2 yn;
        if (has_y) yn = reinterpret_cast<const ulonglong2*>(p + WW)[lane];

        if (d < DD / 2) { acc2(acc_c, cur.x); acc2(acc_c, cur.y); }
        else            { acc2(acc_r, cur.x); acc2(acc_r, cur.y); }

        // x-diffs: 3 intra-float4 + one cross-lane shuffle
        float x0, x1, x2, x3;
        unpack2(cur.x, x0, x1);
        unpack2(cur.y, x2, x3);
        const float nlx = __shfl_down_sync(0xffffffffu, x0, 1);
        sx += fabsf(x1 - x0) + fabsf(x2 - x1) + fabsf(x3 - x2);
        if (lane < 31) sx += fabsf(nlx - x3);

        if (has_y) {
            absdiff_acc2(acc_y, cur.x, yn.x, neg1);
            absdiff_acc2(acc_y, cur.y, yn.y, neg1);
        }
        if (d > 0) {
            absdiff_acc2(acc_z, prev.x, cur.x, neg1);
            absdiff_acc2(acc_z, prev.y, cur.y, neg1);
        }
        prev = cur;
        p += SLICE_STRIDE;
    }

    float crown = hadd2(acc_c);
    float root  = hadd2(acc_r);
    float sy    = hadd2(acc_y);
    float sz    = hadd2(acc_z);

    // warp reduce 5 quantities
    #pragma unroll
    for (int off = 16; off > 0; off >>= 1) {
        crown += __shfl_xor_sync(0xffffffffu, crown, off);
        root  += __shfl_xor_sync(0xffffffffu, root,  off);
        sx    += __shfl_xor_sync(0xffffffffu, sx,    off);
        sy    += __shfl_xor_sync(0xffffffffu, sy,    off);
        sz    += __shfl_xor_sync(0xffffffffu, sz,    off);
    }

    __shared__ float sh[5][8];
    if (lane == 0) {
        sh[0][warp] = crown; sh[1][warp] = root;
        sh[2][warp] = sx;    sh[3][warp] = sy; sh[4][warp] = sz;
    }
    __syncthreads();

    __shared__ bool s_last;
    if (threadIdx.x == 0) {
        float t0 = 0.f, t1 = 0.f, t2 = 0.f, t3 = 0.f, t4 = 0.f;
        #pragma unroll
        for (int w = 0; w < 8; w++) {
            t0 += sh[0][w]; t1 += sh[1][w]; t2 += sh[2][w]; t3 += sh[3][w]; t4 += sh[4][w];
        }
        g_a[cta] = make_float4(t0, t1, t2, t3);
        g_b[cta] = t4;
        __threadfence();
        const unsigned old = atomicAdd(&g_count, 1u);
        s_last = (old == NCTA - 1);
    }
    __syncthreads();
    if (!s_last) return;

    // ---- last CTA does the finalize (no separate kernel, clocks hot) ----
    __threadfence();

    const int tid = threadIdx.x;
    double loss = 0.0, tx = 0.0, ty = 0.0, tz = 0.0;
    if (tid < NBC) {
        double crn = 0.0, rt = 0.0;
        #pragma unroll
        for (int k = 0; k < HBLOCKS; k++) {
            const float4 a = g_a[tid * HBLOCKS + k];
            const float  b = g_b[tid * HBLOCKS + k];
            crn += (double)a.x; rt += (double)a.y;
            tx  += (double)a.z; ty += (double)a.w; tz += (double)b;
        }
        if ((crn + rt) > 0.0 && rt > 0.0) {
            const double r = crn / rt - 1.2;
            loss = r * r;
        }
    }

    #pragma unroll
    for (int off = 16; off > 0; off >>= 1) {
        loss += __shfl_xor_sync(0xffffffffu, loss, off);
        tx   += __shfl_xor_sync(0xffffffffu, tx,   off);
        ty   += __shfl_xor_sync(0xffffffffu, ty,   off);
        tz   += __shfl_xor_sync(0xffffffffu, tz,   off);
    }

    __shared__ double shd[4][8];
    if (lane == 0) {
        shd[0][warp] = loss; shd[1][warp] = tx; shd[2][warp] = ty; shd[3][warp] = tz;
    }
    __syncthreads();

    if (tid == 0) {
        double L = 0.0, Tx = 0.0, Ty = 0.0, Tz = 0.0;
        #pragma unroll
        for (int w = 0; w < 8; w++) {
            L += shd[0][w]; Tx += shd[1][w]; Ty += shd[2][w]; Tz += shd[3][w];
        }
        const double cr_loss = L / (double)NBC;
        const double Nx = (double)BB * CC * DD * HH * (WW - 1);
        const double Ny = (double)BB * CC * DD * (HH - 1) * WW;
        const double Nz = (double)BB * CC * (DD - 1) * HH * WW;
        const double tv = Tx / Nx + Ty / Ny + Tz / Nz;

        const double crown_root = cr_loss * 2.0;   // CROWN_ROOT_W
        const double smooth     = tv * 1.5;        // SMOOTH_W
        out[0] = (float)crown_root;
        out[1] = (float)smooth;
        out[2] = (float)(crown_root + smooth);

        g_count = 0;   // reset for the next graph replay
    }
}

extern "C" void kernel_launch(void* const* d_in, const int* in_sizes, int n_in,
                              void* d_out, int out_size) {
    const float* seg = (const float*)d_in[0];
    float* out = (float*)d_out;
    fused_kernel<<<NCTA, 256>>>(seg, out);
}

// round 5
// speedup vs baseline: 1.5756x; 1.1435x over previous
#include <cuda_runtime.h>

#define BB 2
#define CC 32
#define DD 64
#define HH 128
#define WW 128
#define NBC (BB*CC)
#define SLICE (HH*WW)
#define NCTA 1024            // 64 bc x 8 hblocks x 2 zhalves

// Per-CTA partials [sum, sx, sy, sz]; fully rewritten each run.
__device__ float4 g_part[NCTA];
__device__ unsigned int g_count;   // zero at load; last CTA resets to 0

// ---- packed f32x2 helpers ----
__device__ __forceinline__ void unpack2(unsigned long long v, float& lo, float& hi) {
    asm("mov.b64 {%0,%1}, %2;" : "=f"(lo), "=f"(hi) : "l"(v));
}
__device__ __forceinline__ void acc2(unsigned long long& acc, unsigned long long v) {
    asm("add.rn.f32x2 %0, %0, %1;" : "+l"(acc) : "l"(v));
}
// acc += |b - a| elementwise (packed)
__device__ __forceinline__ void absdiff_acc2(unsigned long long& acc,
                                             unsigned long long a,
                                             unsigned long long b,
                                             unsigned long long neg1) {
    unsigned long long d;
    asm("fma.rn.f32x2 %0, %1, %2, %3;" : "=l"(d) : "l"(a), "l"(neg1), "l"(b)); // b - a
    asm("and.b64 %0, %0, 0x7FFFFFFF7FFFFFFF;" : "+l"(d));
    asm("add.rn.f32x2 %0, %0, %1;" : "+l"(acc) : "l"(d));
}
__device__ __forceinline__ float hadd2(unsigned long long v) {
    float a, b; unpack2(v, a, b); return a + b;
}

struct StepOut { float sx; };

// x-diffs for one row held as (r.x=x0x1, r.y=x2x3)
__device__ __forceinline__ float xdiff_row(const ulonglong2& r, int lane) {
    float x0, x1, x2, x3;
    unpack2(r.x, x0, x1);
    unpack2(r.y, x2, x3);
    const float nlx = __shfl_down_sync(0xffffffffu, x0, 1);
    float s = fabsf(x1 - x0) + fabsf(x2 - x1) + fabsf(x3 - x2);
    if (lane < 31) s += fabsf(nlx - x3);
    return s;
}

// CTA = (bc, 16-row block, z-half). 8 warps; warp w owns rows h0=hb*16+2w, h0+1,
// walking 32 z-slices. y-diff within the pair is register-register; pair-boundary
// y-diff loads row h0+2 (another warp's row -> L1 hit). z-diff uses the prefetched
// next-slice pair (register carry). zh=0 also loads slice 32 once for the seam.
__global__ void __launch_bounds__(256, 7) fused_kernel(const float* __restrict__ seg,
                                                       float* __restrict__ out) {
    const int cta  = blockIdx.x;
    const int bc   = cta >> 4;
    const int rem  = cta & 15;
    const int hb   = rem >> 1;
    const int zh   = rem & 1;
    const int warp = threadIdx.x >> 5;
    const int lane = threadIdx.x & 31;
    const int h0   = hb * 16 + 2 * warp;
    const bool has_y = (h0 + 1 < HH - 1);          // seam row h0+2 exists
    const unsigned long long neg1 = 0xBF800000BF800000ULL;

    const float* p = seg + (size_t)bc * DD * SLICE + (size_t)(zh * 32) * SLICE + h0 * WW;

    unsigned long long acc_s = 0ULL, acc_y = 0ULL, acc_z = 0ULL;
    float sx = 0.f;

    ulonglong2 c0 = reinterpret_cast<const ulonglong2*>(p)[lane];
    ulonglong2 c1 = reinterpret_cast<const ulonglong2*>(p + WW)[lane];

    #pragma unroll 1
    for (int i = 0; i < 31; i++) {
        // prefetch next slice pair + seam row (3 independent loads)
        const ulonglong2 n0 = reinterpret_cast<const ulonglong2*>(p + SLICE)[lane];
        const ulonglong2 n1 = reinterpret_cast<const ulonglong2*>(p + SLICE + WW)[lane];
        ulonglong2 yn;
        if (has_y) yn = reinterpret_cast<const ulonglong2*>(p + 2 * WW)[lane];

        acc2(acc_s, c0.x); acc2(acc_s, c0.y);
        acc2(acc_s, c1.x); acc2(acc_s, c1.y);

        sx += xdiff_row(c0, lane);
        sx += xdiff_row(c1, lane);

        // y: in-pair diff + seam diff
        absdiff_acc2(acc_y, c0.x, c1.x, neg1);
        absdiff_acc2(acc_y, c0.y, c1.y, neg1);
        if (has_y) {
            absdiff_acc2(acc_y, c1.x, yn.x, neg1);
            absdiff_acc2(acc_y, c1.y, yn.y, neg1);
        }

        // z: diff vs prefetched next slice
        absdiff_acc2(acc_z, c0.x, n0.x, neg1);
        absdiff_acc2(acc_z, c0.y, n0.y, neg1);
        absdiff_acc2(acc_z, c1.x, n1.x, neg1);
        absdiff_acc2(acc_z, c1.y, n1.y, neg1);

        c0 = n0; c1 = n1;
        p += SLICE;
    }

    // epilogue: local slice 31 (global d = zh*32 + 31)
    {
        ulonglong2 yn;
        if (has_y) yn = reinterpret_cast<const ulonglong2*>(p + 2 * WW)[lane];

        acc2(acc_s, c0.x); acc2(acc_s, c0.y);
        acc2(acc_s, c1.x); acc2(acc_s, c1.y);
        sx += xdiff_row(c0, lane);
        sx += xdiff_row(c1, lane);
        absdiff_acc2(acc_y, c0.x, c1.x, neg1);
        absdiff_acc2(acc_y, c0.y, c1.y, neg1);
        if (has_y) {
            absdiff_acc2(acc_y, c1.x, yn.x, neg1);
            absdiff_acc2(acc_y, c1.y, yn.y, neg1);
        }
        if (zh == 0) {   // seam z-diff (slice 31 vs 32) owned by left CTA
            const ulonglong2 n0 = reinterpret_cast<const ulonglong2*>(p + SLICE)[lane];
            const ulonglong2 n1 = reinterpret_cast<const ulonglong2*>(p + SLICE + WW)[lane];
            absdiff_acc2(acc_z, c0.x, n0.x, neg1);
            absdiff_acc2(acc_z, c0.y, n0.y, neg1);
            absdiff_acc2(acc_z, c1.x, n1.x, neg1);
            absdiff_acc2(acc_z, c1.y, n1.y, neg1);
        }
    }

    float ssum = hadd2(acc_s);
    float sy   = hadd2(acc_y);
    float sz   = hadd2(acc_z);

    #pragma unroll
    for (int off = 16; off > 0; off >>= 1) {
        ssum += __shfl_xor_sync(0xffffffffu, ssum, off);
        sx   += __shfl_xor_sync(0xffffffffu, sx,   off);
        sy   += __shfl_xor_sync(0xffffffffu, sy,   off);
        sz   += __shfl_xor_sync(0xffffffffu, sz,   off);
    }

    __shared__ float sh[4][8];
    if (lane == 0) { sh[0][warp] = ssum; sh[1][warp] = sx; sh[2][warp] = sy; sh[3][warp] = sz; }
    __syncthreads();

    __shared__ bool s_last;
    if (threadIdx.x == 0) {
        float t0 = 0.f, t1 = 0.f, t2 = 0.f, t3 = 0.f;
        #pragma unroll
        for (int w = 0; w < 8; w++) {
            t0 += sh[0][w]; t1 += sh[1][w]; t2 += sh[2][w]; t3 += sh[3][w];
        }
        g_part[cta] = make_float4(t0, t1, t2, t3);
        __threadfence();
        const unsigned old = atomicAdd(&g_count, 1u);
        s_last = (old == NCTA - 1);
    }
    __syncthreads();
    if (!s_last) return;

    // ---- finalize in the last CTA ----
    __threadfence();

    const int tid = threadIdx.x;
    double loss = 0.0, tx = 0.0, ty = 0.0, tz = 0.0;
    if (tid < NBC) {
        double crn = 0.0, rt = 0.0;
        #pragma unroll
        for (int k = 0; k < 16; k++) {
            const float4 a = g_part[tid * 16 + k];
            if ((k & 1) == 0) crn += (double)a.x;   // zh=0 half -> crown
            else              rt  += (double)a.x;   // zh=1 half -> root
            tx += (double)a.y; ty += (double)a.z; tz += (double)a.w;
        }
        if ((crn + rt) > 0.0 && rt > 0.0) {
            const double r = crn / rt - 1.2;
            loss = r * r;
        }
    }

    #pragma unroll
    for (int off = 16; off > 0; off >>= 1) {
        loss += __shfl_xor_sync(0xffffffffu, loss, off);
        tx   += __shfl_xor_sync(0xffffffffu, tx,   off);
        ty   += __shfl_xor_sync(0xffffffffu, ty,   off);
        tz   += __shfl_xor_sync(0xffffffffu, tz,   off);
    }

    __shared__ double shd[4][8];
    if (lane == 0) { shd[0][warp] = loss; shd[1][warp] = tx; shd[2][warp] = ty; shd[3][warp] = tz; }
    __syncthreads();

    if (tid == 0) {
        double L = 0.0, Tx = 0.0, Ty = 0.0, Tz = 0.0;
        #pragma unroll
        for (int w = 0; w < 8; w++) {
            L += shd[0][w]; Tx += shd[1][w]; Ty += shd[2][w]; Tz += shd[3][w];
        }
        const double cr_loss = L / (double)NBC;
        const double Nx = (double)BB * CC * DD * HH * (WW - 1);
        const double Ny = (double)BB * CC * DD * (HH - 1) * WW;
        const double Nz = (double)BB * CC * (DD - 1) * HH * WW;
        const double tv = Tx / Nx + Ty / Ny + Tz / Nz;

        const double crown_root = cr_loss * 2.0;   // CROWN_ROOT_W
        const double smooth     = tv * 1.5;        // SMOOTH_W
        out[0] = (float)crown_root;
        out[1] = (float)smooth;
        out[2] = (float)(crown_root + smooth);

        g_count = 0;   // reset for next graph replay
    }
}

extern "C" void kernel_launch(void* const* d_in, const int* in_sizes, int n_in,
                              void* d_out, int out_size) {
    const float* seg = (const float*)d_in[0];
    float* out = (float*)d_out;
    fused_kernel<<<NCTA, 256>>>(seg, out);
}

// round 6
// speedup vs baseline: 1.6380x; 1.0396x over previous
#include <cuda_runtime.h>

#define BB 2
#define CC 32
#define DD 64
#define HH 128
#define WW 128
#define NBC (BB*CC)
#define SLICE (HH*WW)
#define NCTA 512             // 64 bc x 4 hblocks(32 rows) x 2 zhalves

// Per-CTA partials [sum, sx, sy, sz]; fully rewritten each run.
__device__ float4 g_part[NCTA];
__device__ unsigned int g_count;   // zero at load; last CTA resets to 0

// ---- packed f32x2 helpers ----
__device__ __forceinline__ void unpack2(unsigned long long v, float& lo, float& hi) {
    asm("mov.b64 {%0,%1}, %2;" : "=f"(lo), "=f"(hi) : "l"(v));
}
__device__ __forceinline__ void acc2(unsigned long long& acc, unsigned long long v) {
    asm("add.rn.f32x2 %0, %0, %1;" : "+l"(acc) : "l"(v));
}
// acc += |b - a| elementwise (packed)
__device__ __forceinline__ void absdiff_acc2(unsigned long long& acc,
                                             unsigned long long a,
                                             unsigned long long b,
                                             unsigned long long neg1) {
    unsigned long long d;
    asm("fma.rn.f32x2 %0, %1, %2, %3;" : "=l"(d) : "l"(a), "l"(neg1), "l"(b)); // b - a
    asm("and.b64 %0, %0, 0x7FFFFFFF7FFFFFFF;" : "+l"(d));
    asm("add.rn.f32x2 %0, %0, %1;" : "+l"(acc) : "l"(d));
}
__device__ __forceinline__ float hadd2(unsigned long long v) {
    float a, b; unpack2(v, a, b); return a + b;
}

// x-diffs for one row held as (r.x=x0x1, r.y=x2x3)
__device__ __forceinline__ float xdiff_row(const ulonglong2& r, int lane) {
    float x0, x1, x2, x3;
    unpack2(r.x, x0, x1);
    unpack2(r.y, x2, x3);
    const float nlx = __shfl_down_sync(0xffffffffu, x0, 1);
    float s = fabsf(x1 - x0) + fabsf(x2 - x1) + fabsf(x3 - x2);
    if (lane < 31) s += fabsf(nlx - x3);
    return s;
}

// CTA = (bc, 32-row block, z-half). 8 warps; warp w carries 4 consecutive rows
// h0..h0+3 across 32 z-slices. 3 of 4 y-diffs are register-register; the seam
// y-diff loads row h0+4 (next warp's row -> L1 hit). z-diff uses the prefetched
// next-slice quad. zh=0 additionally loads slice 32 once for the z seam.
__global__ void __launch_bounds__(256) fused_kernel(const float* __restrict__ seg,
                                                    float* __restrict__ out) {
    const int cta  = blockIdx.x;
    const int bc   = cta >> 3;
    const int rem  = cta & 7;
    const int hb   = rem >> 1;           // 0..3 (32-row blocks)
    const int zh   = rem & 1;
    const int warp = threadIdx.x >> 5;
    const int lane = threadIdx.x & 31;
    const int h0   = hb * 32 + warp * 4;
    const bool has_y = (h0 + 4 < HH);    // seam row h0+4 exists (false only for rows 124..127)
    const unsigned long long neg1 = 0xBF800000BF800000ULL;

    const float* p = seg + (size_t)bc * DD * SLICE + (size_t)(zh * 32) * SLICE + h0 * WW;

    unsigned long long acc_s = 0ULL, acc_y = 0ULL, acc_z = 0ULL;
    float sx = 0.f;

    ulonglong2 c[4];
    #pragma unroll
    for (int r = 0; r < 4; r++)
        c[r] = reinterpret_cast<const ulonglong2*>(p + r * WW)[lane];

    #pragma unroll 1
    for (int i = 0; i < 31; i++) {
        // prefetch next-slice quad + y-seam row (5 independent loads)
        ulonglong2 n[4];
        #pragma unroll
        for (int r = 0; r < 4; r++)
            n[r] = reinterpret_cast<const ulonglong2*>(p + SLICE + r * WW)[lane];
        ulonglong2 yn;
        if (has_y) yn = reinterpret_cast<const ulonglong2*>(p + 4 * WW)[lane];

        // slice sums + x-diffs
        #pragma unroll
        for (int r = 0; r < 4; r++) {
            acc2(acc_s, c[r].x); acc2(acc_s, c[r].y);
            sx += xdiff_row(c[r], lane);
        }
        // y: 3 in-quad diffs + seam
        #pragma unroll
        for (int r = 0; r < 3; r++) {
            absdiff_acc2(acc_y, c[r].x, c[r + 1].x, neg1);
            absdiff_acc2(acc_y, c[r].y, c[r + 1].y, neg1);
        }
        if (has_y) {
            absdiff_acc2(acc_y, c[3].x, yn.x, neg1);
            absdiff_acc2(acc_y, c[3].y, yn.y, neg1);
        }
        // z: diff vs prefetched next slice
        #pragma unroll
        for (int r = 0; r < 4; r++) {
            absdiff_acc2(acc_z, c[r].x, n[r].x, neg1);
            absdiff_acc2(acc_z, c[r].y, n[r].y, neg1);
            c[r] = n[r];
        }
        p += SLICE;
    }

    // epilogue: local slice 31 (global d = zh*32 + 31)
    {
        ulonglong2 yn;
        if (has_y) yn = reinterpret_cast<const ulonglong2*>(p + 4 * WW)[lane];

        #pragma unroll
        for (int r = 0; r < 4; r++) {
            acc2(acc_s, c[r].x); acc2(acc_s, c[r].y);
            sx += xdiff_row(c[r], lane);
        }
        #pragma unroll
        for (int r = 0; r < 3; r++) {
            absdiff_acc2(acc_y, c[r].x, c[r + 1].x, neg1);
            absdiff_acc2(acc_y, c[r].y, c[r + 1].y, neg1);
        }
        if (has_y) {
            absdiff_acc2(acc_y, c[3].x, yn.x, neg1);
            absdiff_acc2(acc_y, c[3].y, yn.y, neg1);
        }
        if (zh == 0) {   // z seam (slice 31 vs 32) owned by left CTA
            #pragma unroll
            for (int r = 0; r < 4; r++) {
                const ulonglong2 n = reinterpret_cast<const ulonglong2*>(p + SLICE + r * WW)[lane];
                absdiff_acc2(acc_z, c[r].x, n.x, neg1);
                absdiff_acc2(acc_z, c[r].y, n.y, neg1);
            }
        }
    }

    float ssum = hadd2(acc_s);
    float sy   = hadd2(acc_y);
    float sz   = hadd2(acc_z);

    #pragma unroll
    for (int off = 16; off > 0; off >>= 1) {
        ssum += __shfl_xor_sync(0xffffffffu, ssum, off);
        sx   += __shfl_xor_sync(0xffffffffu, sx,   off);
        sy   += __shfl_xor_sync(0xffffffffu, sy,   off);
        sz   += __shfl_xor_sync(0xffffffffu, sz,   off);
    }

    __shared__ float sh[4][8];
    if (lane == 0) { sh[0][warp] = ssum; sh[1][warp] = sx; sh[2][warp] = sy; sh[3][warp] = sz; }
    __syncthreads();

    __shared__ bool s_last;
    if (threadIdx.x == 0) {
        float t0 = 0.f, t1 = 0.f, t2 = 0.f, t3 = 0.f;
        #pragma unroll
        for (int w = 0; w < 8; w++) {
            t0 += sh[0][w]; t1 += sh[1][w]; t2 += sh[2][w]; t3 += sh[3][w];
        }
        g_part[cta] = make_float4(t0, t1, t2, t3);
        __threadfence();
        const unsigned old = atomicAdd(&g_count, 1u);
        s_last = (old == NCTA - 1);
    }
    __syncthreads();
    if (!s_last) return;

    // ---- finalize in the last CTA ----
    __threadfence();

    const int tid = threadIdx.x;
    double loss = 0.0, tx = 0.0, ty = 0.0, tz = 0.0;
    if (tid < NBC) {
        double crn = 0.0, rt = 0.0;
        #pragma unroll
        for (int k = 0; k < 8; k++) {          // 4 hblocks x 2 zhalves
            const float4 a = g_part[tid * 8 + k];
            if ((k & 1) == 0) crn += (double)a.x;   // zh=0 -> crown (d 0..31)
            else              rt  += (double)a.x;   // zh=1 -> root  (d 32..63)
            tx += (double)a.y; ty += (double)a.z; tz += (double)a.w;
        }
        if ((crn + rt) > 0.0 && rt > 0.0) {
            const double r = crn / rt - 1.2;
            loss = r * r;
        }
    }

    #pragma unroll
    for (int off = 16; off > 0; off >>= 1) {
        loss += __shfl_xor_sync(0xffffffffu, loss, off);
        tx   += __shfl_xor_sync(0xffffffffu, tx,   off);
        ty   += __shfl_xor_sync(0xffffffffu, ty,   off);
        tz   += __shfl_xor_sync(0xffffffffu, tz,   off);
    }

    __shared__ double shd[4][8];
    if (lane == 0) { shd[0][warp] = loss; shd[1][warp] = tx; shd[2][warp] = ty; shd[3][warp] = tz; }
    __syncthreads();

    if (tid == 0) {
        double L = 0.0, Tx = 0.0, Ty = 0.0, Tz = 0.0;
        #pragma unroll
        for (int w = 0; w < 8; w++) {
            L += shd[0][w]; Tx += shd[1][w]; Ty += shd[2][w]; Tz += shd[3][w];
        }
        const double cr_loss = L / (double)NBC;
        const double Nx = (double)BB * CC * DD * HH * (WW - 1);
        const double Ny = (double)BB * CC * DD * (HH - 1) * WW;
        const double Nz = (double)BB * CC * (DD - 1) * HH * WW;
        const double tv = Tx / Nx + Ty / Ny + Tz / Nz;

        const double crown_root = cr_loss * 2.0;   // CROWN_ROOT_W
        const double smooth     = tv * 1.5;        // SMOOTH_W
        out[0] = (float)crown_root;
        out[1] = (float)smooth;
        out[2] = (float)(crown_root + smooth);

        g_count = 0;   // reset for next graph replay
    }
}

extern "C" void kernel_launch(void* const* d_in, const int* in_sizes, int n_in,
                              void* d_out, int out_size) {
    const float* seg = (const float*)d_in[0];
    float* out = (float*)d_out;
    fused_kernel<<<NCTA, 256>>>(seg, out);
}